// round 6
// baseline (speedup 1.0000x reference)
#include <cuda_runtime.h>
#include <cuda_bf16.h>

// ---------------------------------------------------------------------------
// SynthesisConv (StyleGAN2): modulated transposed conv up=2 + FIR + noise
//   B=16, Cin=Cout=512, H=W=32, K=3, out [16,512,64,64] fp32
//
// Decomposition:
//   style[b,ci]  = w_latent[b]·affine_weight[ci]/sqrt(512) + affine_bias[ci]
//   dcoef[b,co]  = rsqrt( sum_ci style^2 * (sum_tap w^2) + 1e-8 )
//   Z[b,tap,co,s]= sum_ci W[co,ci,tap] * (x*style)[b,ci,s]   (TF32 GEMM)
//   y1[2i+kh,2j+kw] += Z[kh*3+kw][i,j] * dcoef               (implicit)
//   out = clamp(lrelu(FIR(y1) + noise*ns + bias)*sqrt2, +-256)
// FIR folded into per-parity 2-tap 1D coefficients -> 36-term gather on Z.
// ---------------------------------------------------------------------------

#define BATCH 16
#define CIN   512
#define COUT  512
#define HSP   1024          // 32*32 input spatial
#define MTOT  4608          // 9*512
#define NTOT  1024

__device__ float g_style[BATCH*CIN];
__device__ float g_dcoef[BATCH*COUT];
__device__ float g_A[MTOT*CIN];                  // 9.4 MB  (tf32 weights, [tap*512+co][ci])
__device__ float g_xs[BATCH*CIN*HSP];            // 33.5 MB (tf32 x*style)
__device__ float g_Z[(size_t)BATCH*MTOT*NTOT];   // 302 MB  (fp32 tap GEMM outputs)

__device__ __forceinline__ float tf32r(float f) {
    unsigned int u;
    asm("cvt.rna.tf32.f32 %0, %1;" : "=r"(u) : "f"(f));
    return __uint_as_float(u);
}

__device__ __forceinline__ void cp_async16(void* smem, const void* gmem) {
    unsigned int s = (unsigned int)__cvta_generic_to_shared(smem);
    asm volatile("cp.async.ca.shared.global [%0], [%1], 16;\n" :: "r"(s), "l"(gmem));
}

__device__ __forceinline__ void mma_tf32(float* c, const unsigned int* a, const unsigned int* b) {
    asm volatile(
        "mma.sync.aligned.m16n8k8.row.col.f32.tf32.tf32.f32 "
        "{%0,%1,%2,%3}, {%4,%5,%6,%7}, {%8,%9}, {%0,%1,%2,%3};\n"
        : "+f"(c[0]), "+f"(c[1]), "+f"(c[2]), "+f"(c[3])
        : "r"(a[0]), "r"(a[1]), "r"(a[2]), "r"(a[3]), "r"(b[0]), "r"(b[1]));
}

// ---------------------------------------------------------------------------
// K1a: style[b,ci]
// ---------------------------------------------------------------------------
__global__ void style_kernel(const float* __restrict__ wl,
                             const float* __restrict__ aw,
                             const float* __restrict__ ab) {
    int b   = blockIdx.y;
    int tid = threadIdx.x;
    int ci  = blockIdx.x * 128 + tid;
    __shared__ float s[512];
    for (int i = tid; i < 512; i += 128) s[i] = wl[b*512 + i];
    __syncthreads();
    const float4* row = (const float4*)(aw + (size_t)ci * 512);
    const float4* sw  = (const float4*)s;
    float acc = 0.f;
    #pragma unroll 4
    for (int j = 0; j < 128; j++) {
        float4 v = row[j];
        float4 w = sw[j];
        acc += v.x*w.x + v.y*w.y + v.z*w.z + v.w*w.w;
    }
    g_style[b*512 + ci] = acc * 0.04419417382415922f + ab[ci];  // 1/sqrt(512)
}

// ---------------------------------------------------------------------------
// K1b: per-co: repack weights to TF32 A[tap*512+co][ci], compute dcoef[b,co]
// ---------------------------------------------------------------------------
__global__ void wprep_kernel(const float* __restrict__ cw) {
    int co = blockIdx.x;
    int ci = threadIdx.x;            // 512 threads
    const float* wrow = cw + ((size_t)co * 512 + ci) * 9;
    float w[9];
    float wsq = 0.f;
    #pragma unroll
    for (int t = 0; t < 9; t++) { w[t] = wrow[t]; wsq += w[t]*w[t]; }
    #pragma unroll
    for (int t = 0; t < 9; t++)
        g_A[((size_t)(t*512 + co)) * 512 + ci] = tf32r(w[t]);

    __shared__ float red[16];
    int lane = ci & 31, warp = ci >> 5;
    for (int b = 0; b < 16; b++) {
        float s = g_style[b*512 + ci];
        float v = s * s * wsq;
        #pragma unroll
        for (int o = 16; o; o >>= 1) v += __shfl_xor_sync(0xffffffffu, v, o);
        if (lane == 0) red[warp] = v;
        __syncthreads();
        if (ci == 0) {
            float tot = 0.f;
            #pragma unroll
            for (int k = 0; k < 16; k++) tot += red[k];
            g_dcoef[b*512 + co] = rsqrtf(tot + 1e-8f);
        }
        __syncthreads();
    }
}

// ---------------------------------------------------------------------------
// K1c: xs = tf32(x * style)
// ---------------------------------------------------------------------------
__global__ void xs_kernel(const float* __restrict__ x) {
    int idx = blockIdx.x * 256 + threadIdx.x;      // float4 index, 2097152 total
    float4 v = ((const float4*)x)[idx];
    float s = g_style[idx >> 8];                   // 256 float4 per (b,ci)
    float4 o;
    o.x = tf32r(v.x * s); o.y = tf32r(v.y * s);
    o.z = tf32r(v.z * s); o.w = tf32r(v.w * s);
    ((float4*)g_xs)[idx] = o;
}

// ---------------------------------------------------------------------------
// K2: batched TF32 GEMM  Z[b] (4608x1024) = A (4608x512) * xs[b] (512x1024)
//     epilogue: row scale by dcoef[b, m%512]
// Tiles: BM=128 BN=128 BK=16, 256 thr, 8 warps (4x2), warp tile 32x64.
// ---------------------------------------------------------------------------
#define BK 16
__global__ __launch_bounds__(256, 2) void gemm_kernel() {
    __shared__ float As[2][128][20];    // pad 20 -> conflict-free frag loads
    __shared__ float Bs[2][BK][136];    // pad 136 -> conflict-free frag loads

    int tid = threadIdx.x;
    int bN = blockIdx.x, bM = blockIdx.y, b = blockIdx.z;
    int wid = tid >> 5, lane = tid & 31;
    int wM = (wid & 3) * 32, wN = (wid >> 2) * 64;
    int gid = lane >> 2, tig = lane & 3;

    const float* Ag = g_A + (size_t)bM * 128 * 512;
    const float* Bg = g_xs + (size_t)b * 512 * 1024 + bN * 128;

    int ar = tid >> 2;          // 0..63
    int ac = (tid & 3) * 4;
    int br = tid >> 5;          // 0..7
    int bc = (tid & 31) * 4;

    float c[2][8][4];
    #pragma unroll
    for (int i = 0; i < 2; i++)
        #pragma unroll
        for (int j = 0; j < 8; j++)
            #pragma unroll
            for (int k = 0; k < 4; k++) c[i][j][k] = 0.f;

    // stage 0 loads
    #pragma unroll
    for (int p = 0; p < 2; p++)
        cp_async16(&As[0][ar + p*64][ac], Ag + (size_t)(ar + p*64)*512 + 0 + ac);
    #pragma unroll
    for (int p = 0; p < 2; p++)
        cp_async16(&Bs[0][br + p*8][bc], Bg + (size_t)(0 + br + p*8)*1024 + bc);
    asm volatile("cp.async.commit_group;\n");

    for (int kt = 0; kt < 32; ++kt) {
        int cur = kt & 1;
        if (kt < 31) {
            int nxt = cur ^ 1;
            int k0 = (kt + 1) * BK;
            #pragma unroll
            for (int p = 0; p < 2; p++)
                cp_async16(&As[nxt][ar + p*64][ac], Ag + (size_t)(ar + p*64)*512 + k0 + ac);
            #pragma unroll
            for (int p = 0; p < 2; p++)
                cp_async16(&Bs[nxt][br + p*8][bc], Bg + (size_t)(k0 + br + p*8)*1024 + bc);
            asm volatile("cp.async.commit_group;\n");
            asm volatile("cp.async.wait_group 1;\n");
        } else {
            asm volatile("cp.async.wait_group 0;\n");
        }
        __syncthreads();

        #pragma unroll
        for (int ks = 0; ks < 2; ks++) {
            int k8 = ks * 8;
            unsigned int a[2][4], bb[8][2];
            #pragma unroll
            for (int i = 0; i < 2; i++) {
                int mb = wM + i * 16;
                a[i][0] = __float_as_uint(As[cur][mb + gid    ][k8 + tig    ]);
                a[i][1] = __float_as_uint(As[cur][mb + gid + 8][k8 + tig    ]);
                a[i][2] = __float_as_uint(As[cur][mb + gid    ][k8 + tig + 4]);
                a[i][3] = __float_as_uint(As[cur][mb + gid + 8][k8 + tig + 4]);
            }
            #pragma unroll
            for (int j = 0; j < 8; j++) {
                int nb = wN + j * 8 + gid;
                bb[j][0] = __float_as_uint(Bs[cur][k8 + tig    ][nb]);
                bb[j][1] = __float_as_uint(Bs[cur][k8 + tig + 4][nb]);
            }
            #pragma unroll
            for (int i = 0; i < 2; i++)
                #pragma unroll
                for (int j = 0; j < 8; j++)
                    mma_tf32(c[i][j], a[i], bb[j]);
        }
        __syncthreads();
    }

    // epilogue: scale by dcoef, write Z
    size_t zbase = (size_t)b * MTOT * NTOT;
    #pragma unroll
    for (int i = 0; i < 2; i++) {
        int r0 = bM * 128 + wM + i * 16 + gid;
        int r1 = r0 + 8;
        float s0 = g_dcoef[b*512 + (r0 & 511)];
        float s1 = g_dcoef[b*512 + (r1 & 511)];
        #pragma unroll
        for (int j = 0; j < 8; j++) {
            int n = bN * 128 + wN + j * 8 + tig * 2;
            float2 v0 = make_float2(c[i][j][0] * s0, c[i][j][1] * s0);
            float2 v1 = make_float2(c[i][j][2] * s1, c[i][j][3] * s1);
            *(float2*)(g_Z + zbase + (size_t)r0 * 1024 + n) = v0;
            *(float2*)(g_Z + zbase + (size_t)r1 * 1024 + n) = v1;
        }
    }
}

// ---------------------------------------------------------------------------
// K3: upsample-scatter + FIR + noise + bias + lrelu + clamp, per (b,co) block.
//   y[2m+ry, 2n+rx] = sum_{kh,kw} sum_{dy,dx in 0..2}
//       cf[ry][kh][dy] * cf[rx][kw][dx] * Z[kh*3+kw][m-1+dy, n-1+dx]
// ---------------------------------------------------------------------------
__global__ void fir_kernel(const float* __restrict__ noise,
                           const float* __restrict__ nstr,
                           const float* __restrict__ bias,
                           float* __restrict__ out) {
    int co = blockIdx.x, b = blockIdx.y, tid = threadIdx.x;
    __shared__ float Zs[9][34][34];
    float* zf = &Zs[0][0][0];
    for (int i = tid; i < 9 * 34 * 34; i += 256) zf[i] = 0.f;
    __syncthreads();

    #pragma unroll
    for (int t = 0; t < 9; t++) {
        const float4 v = *(const float4*)(g_Z + (((size_t)(b*9 + t) * 512 + co) << 10) + tid * 4);
        int iy = tid >> 3;
        int ix = (tid & 7) * 4;
        Zs[t][1 + iy][1 + ix] = v.x;
        Zs[t][1 + iy][2 + ix] = v.y;
        Zs[t][1 + iy][3 + ix] = v.z;
        Zs[t][1 + iy][4 + ix] = v.w;
    }
    __syncthreads();

    float ns = nstr[0], bi = bias[co];
    // cf[parity r][kh][dy]: fractional-upsample FIR coefficients, f1n={.25,.75,.75,.25}
    const float cf[2][3][3] = {
        { {0.00f, 0.75f, 0.25f}, {0.25f, 0.75f, 0.00f}, {0.75f, 0.25f, 0.00f} },
        { {0.00f, 0.25f, 0.75f}, {0.00f, 0.75f, 0.25f}, {0.25f, 0.75f, 0.00f} }
    };
    size_t obase = ((size_t)(b * 512 + co)) << 12;

    for (int q = tid; q < 1024; q += 256) {
        int m = q >> 5, n = q & 31;
        float a00 = 0.f, a01 = 0.f, a10 = 0.f, a11 = 0.f;
        #pragma unroll
        for (int kh = 0; kh < 3; kh++) {
            #pragma unroll
            for (int kw = 0; kw < 3; kw++) {
                float z[3][3];
                #pragma unroll
                for (int dy = 0; dy < 3; dy++)
                    #pragma unroll
                    for (int dx = 0; dx < 3; dx++)
                        z[dy][dx] = Zs[kh * 3 + kw][m + dy][n + dx];
                #pragma unroll
                for (int dx = 0; dx < 3; dx++) {
                    float r0 = cf[0][kh][0]*z[0][dx] + cf[0][kh][1]*z[1][dx] + cf[0][kh][2]*z[2][dx];
                    float r1 = cf[1][kh][0]*z[0][dx] + cf[1][kh][1]*z[1][dx] + cf[1][kh][2]*z[2][dx];
                    a00 += cf[0][kw][dx] * r0;
                    a01 += cf[1][kw][dx] * r0;
                    a10 += cf[0][kw][dx] * r1;
                    a11 += cf[1][kw][dx] * r1;
                }
            }
        }
        int Y = 2 * m, X = 2 * n;
        float v00 = a00 + noise[(b << 12) + (Y << 6) + X    ] * ns + bi;
        float v01 = a01 + noise[(b << 12) + (Y << 6) + X + 1] * ns + bi;
        float v10 = a10 + noise[(b << 12) + ((Y+1) << 6) + X    ] * ns + bi;
        float v11 = a11 + noise[(b << 12) + ((Y+1) << 6) + X + 1] * ns + bi;
        v00 = (v00 > 0.f ? v00 : 0.2f * v00) * 1.4142135623730951f;
        v01 = (v01 > 0.f ? v01 : 0.2f * v01) * 1.4142135623730951f;
        v10 = (v10 > 0.f ? v10 : 0.2f * v10) * 1.4142135623730951f;
        v11 = (v11 > 0.f ? v11 : 0.2f * v11) * 1.4142135623730951f;
        v00 = fminf(fmaxf(v00, -256.f), 256.f);
        v01 = fminf(fmaxf(v01, -256.f), 256.f);
        v10 = fminf(fmaxf(v10, -256.f), 256.f);
        v11 = fminf(fmaxf(v11, -256.f), 256.f);
        *(float2*)(out + obase + (size_t)Y * 64 + X)       = make_float2(v00, v01);
        *(float2*)(out + obase + (size_t)(Y + 1) * 64 + X) = make_float2(v10, v11);
    }
}

// ---------------------------------------------------------------------------
extern "C" void kernel_launch(void* const* d_in, const int* in_sizes, int n_in,
                              void* d_out, int out_size) {
    const float* x     = (const float*)d_in[0];
    const float* wl    = (const float*)d_in[1];
    const float* aw    = (const float*)d_in[2];
    const float* ab    = (const float*)d_in[3];
    const float* cw    = (const float*)d_in[4];
    const float* noise = (const float*)d_in[5];
    const float* nstr  = (const float*)d_in[6];
    const float* bias  = (const float*)d_in[7];
    float* out = (float*)d_out;

    style_kernel<<<dim3(4, 16), 128>>>(wl, aw, ab);
    wprep_kernel<<<512, 512>>>(cw);
    xs_kernel<<<8192, 256>>>(x);
    gemm_kernel<<<dim3(8, 36, 16), 256>>>();
    fir_kernel<<<dim3(512, 16), 256>>>(noise, nstr, bias, out);
}

// round 8
// speedup vs baseline: 1.5812x; 1.5812x over previous
#include <cuda_runtime.h>
#include <cuda_fp16.h>
#include <cuda_bf16.h>

// ---------------------------------------------------------------------------
// SynthesisConv (StyleGAN2): modulated transposed conv up=2 + FIR + noise
//   B=16, Cin=Cout=512, H=W=32, K=3, out [16,512,64,64] fp32
//
//   style[b,ci]  = w_latent[b]·affine_weight[ci]/sqrt(512) + affine_bias[ci]
//   dcoef[b,co]  = rsqrt( sum_ci style^2 * (sum_tap w^2) + 1e-8 )
//   Z[b,tap,co,s]= dcoef * sum_ci W[co,ci,tap] * (x*style)[b,ci,s]  (FP16 GEMM)
//   out = clamp(lrelu(FIR_gather(Z) + noise*ns + bias)*sqrt2, +-256)
// ---------------------------------------------------------------------------

#define BATCH 16
#define CIN   512
#define COUT  512
#define HSP   1024          // 32*32 input spatial
#define MTOT  4608          // 9*512
#define NTOT  1024

__device__ float  g_style[BATCH*CIN];
__device__ float  g_dcoef[BATCH*COUT];
__device__ __half g_Ah[MTOT*CIN];                  // 4.7 MB  weights [tap*512+co][ci]
__device__ __half g_xsh[BATCH*CIN*HSP];            // 16.8 MB x*style, (ci,ci+1) pair-interleaved
__device__ __half g_Zh[(size_t)BATCH*MTOT*NTOT];   // 151 MB  tap GEMM outputs (post-dcoef)

__device__ __forceinline__ void cp_async16(void* smem, const void* gmem) {
    unsigned int s = (unsigned int)__cvta_generic_to_shared(smem);
    asm volatile("cp.async.cg.shared.global [%0], [%1], 16;\n" :: "r"(s), "l"(gmem));
}

__device__ __forceinline__ void mma_f16(float* c, const unsigned int* a, const unsigned int* b) {
    asm volatile(
        "mma.sync.aligned.m16n8k16.row.col.f32.f16.f16.f32 "
        "{%0,%1,%2,%3}, {%4,%5,%6,%7}, {%8,%9}, {%0,%1,%2,%3};\n"
        : "+f"(c[0]), "+f"(c[1]), "+f"(c[2]), "+f"(c[3])
        : "r"(a[0]), "r"(a[1]), "r"(a[2]), "r"(a[3]), "r"(b[0]), "r"(b[1]));
}

// ---------------------------------------------------------------------------
// K1a: style[b,ci]
// ---------------------------------------------------------------------------
__global__ void style_kernel(const float* __restrict__ wl,
                             const float* __restrict__ aw,
                             const float* __restrict__ ab) {
    int b   = blockIdx.y;
    int tid = threadIdx.x;
    int ci  = blockIdx.x * 128 + tid;
    __shared__ float s[512];
    for (int i = tid; i < 512; i += 128) s[i] = wl[b*512 + i];
    __syncthreads();
    const float4* row = (const float4*)(aw + (size_t)ci * 512);
    const float4* sw  = (const float4*)s;
    float acc = 0.f;
    #pragma unroll 4
    for (int j = 0; j < 128; j++) {
        float4 v = row[j];
        float4 w = sw[j];
        acc += v.x*w.x + v.y*w.y + v.z*w.z + v.w*w.w;
    }
    g_style[b*512 + ci] = acc * 0.04419417382415922f + ab[ci];  // 1/sqrt(512)
}

// ---------------------------------------------------------------------------
// K1b: per-co: repack weights to fp16 A[tap*512+co][ci], compute dcoef[b,co]
// ---------------------------------------------------------------------------
__global__ void wprep_kernel(const float* __restrict__ cw) {
    int co = blockIdx.x;
    int ci = threadIdx.x;            // 512 threads
    const float* wrow = cw + ((size_t)co * 512 + ci) * 9;
    float w[9];
    float wsq = 0.f;
    #pragma unroll
    for (int t = 0; t < 9; t++) { w[t] = wrow[t]; wsq += w[t]*w[t]; }
    #pragma unroll
    for (int t = 0; t < 9; t++)
        g_Ah[((size_t)(t*512 + co)) * 512 + ci] = __float2half_rn(w[t]);

    __shared__ float red[16];
    int lane = ci & 31, warp = ci >> 5;
    for (int b = 0; b < 16; b++) {
        float s = g_style[b*512 + ci];
        float v = s * s * wsq;
        #pragma unroll
        for (int o = 16; o; o >>= 1) v += __shfl_xor_sync(0xffffffffu, v, o);
        if (lane == 0) red[warp] = v;
        __syncthreads();
        if (ci == 0) {
            float tot = 0.f;
            #pragma unroll
            for (int k = 0; k < 16; k++) tot += red[k];
            g_dcoef[b*512 + co] = rsqrtf(tot + 1e-8f);
        }
        __syncthreads();
    }
}

// ---------------------------------------------------------------------------
// K1c: xs = fp16(x * style), pair-interleaved: word (b,kp,s) = (ci=2kp, ci=2kp+1)
// ---------------------------------------------------------------------------
__global__ void xs_kernel(const float* __restrict__ x) {
    int idx = blockIdx.x * 256 + threadIdx.x;   // 1,048,576 total; each does 4 s
    int s4  = (idx & 255) * 4;
    int bkp = idx >> 8;                         // b*256 + kp
    int b   = bkp >> 8;
    int kp  = bkp & 255;
    const float4 v0 = *(const float4*)(x + ((size_t)(b*512 + 2*kp    ) * 1024 + s4));
    const float4 v1 = *(const float4*)(x + ((size_t)(b*512 + 2*kp + 1) * 1024 + s4));
    float s0 = g_style[b*512 + 2*kp];
    float s1 = g_style[b*512 + 2*kp + 1];
    __half2 h0 = __floats2half2_rn(v0.x*s0, v1.x*s1);
    __half2 h1 = __floats2half2_rn(v0.y*s0, v1.y*s1);
    __half2 h2 = __floats2half2_rn(v0.z*s0, v1.z*s1);
    __half2 h3 = __floats2half2_rn(v0.w*s0, v1.w*s1);
    uint4 o;
    o.x = *(unsigned int*)&h0;
    o.y = *(unsigned int*)&h1;
    o.z = *(unsigned int*)&h2;
    o.w = *(unsigned int*)&h3;
    ((uint4*)g_xsh)[idx] = o;
}

// ---------------------------------------------------------------------------
// K2: batched FP16 GEMM  Z[b] (4608x1024) = A (4608x512) * xs[b] (512x1024)
//     epilogue: row scale by dcoef[b, m%512], store fp16.
// BM=128 BN=128 BK=16, 128 threads (4 warps 2x2), warp tile 64x64,
// 4-stage cp.async pipeline, one __syncthreads per k-tile.
// ---------------------------------------------------------------------------
#define PGA 12
#define PGB 136
__global__ __launch_bounds__(128, 2) void gemm_kernel() {
    __shared__ unsigned int As[4][128][PGA];   // 16 halves/row as 8 u32, pitch 12
    __shared__ unsigned int Bs[4][8][PGB];     // 8 ci-pair rows x 128 cols, pitch 136

    int tid = threadIdx.x;
    int bN = blockIdx.x, bM = blockIdx.y, b = blockIdx.z;
    int wid = tid >> 5, lane = tid & 31;
    int wM = (wid & 1) * 64, wN = (wid >> 1) * 64;
    int gid = lane >> 2, tig = lane & 3;

    const unsigned int* Ag = ((const unsigned int*)g_Ah) + (size_t)bM * 32768 + tid * 256;
    const unsigned int* Bg = ((const unsigned int*)g_xsh) + (size_t)b * 262144 + bN * 128;

    int br0 = (tid * 2) >> 5;          // B cp rows for this thread
    int bc0 = ((tid * 2) & 31) * 4;
    int br1 = (tid * 2 + 1) >> 5;
    int bc1 = ((tid * 2 + 1) & 31) * 4;

    float c[4][8][4];
    #pragma unroll
    for (int i = 0; i < 4; i++)
        #pragma unroll
        for (int j = 0; j < 8; j++)
            #pragma unroll
            for (int k = 0; k < 4; k++) c[i][j][k] = 0.f;

    // prologue: stages 0..2
    #pragma unroll
    for (int kt = 0; kt < 3; kt++) {
        cp_async16(&As[kt][tid][0], Ag + kt * 8);
        cp_async16(&As[kt][tid][4], Ag + kt * 8 + 4);
        cp_async16(&Bs[kt][br0][bc0], Bg + (size_t)(kt * 8 + br0) * 1024 + bc0);
        cp_async16(&Bs[kt][br1][bc1], Bg + (size_t)(kt * 8 + br1) * 1024 + bc1);
        asm volatile("cp.async.commit_group;\n");
    }

    for (int kt = 0; kt < 32; kt++) {
        if (kt < 30) asm volatile("cp.async.wait_group 2;\n");
        else         asm volatile("cp.async.wait_group 0;\n");
        __syncthreads();

        int cur = kt & 3;
        unsigned int a[4][4], bb[8][2];
        #pragma unroll
        for (int i = 0; i < 4; i++) {
            int mb = wM + i * 16;
            a[i][0] = As[cur][mb + gid    ][tig    ];
            a[i][1] = As[cur][mb + gid + 8][tig    ];
            a[i][2] = As[cur][mb + gid    ][tig + 4];
            a[i][3] = As[cur][mb + gid + 8][tig + 4];
        }
        #pragma unroll
        for (int j = 0; j < 8; j++) {
            int nb = wN + j * 8 + gid;
            bb[j][0] = Bs[cur][tig    ][nb];
            bb[j][1] = Bs[cur][tig + 4][nb];
        }
        #pragma unroll
        for (int i = 0; i < 4; i++)
            #pragma unroll
            for (int j = 0; j < 8; j++)
                mma_f16(c[i][j], a[i], bb[j]);

        if (kt < 29) {
            int st = (kt + 3) & 3;
            int k0 = (kt + 3) * 8;
            cp_async16(&As[st][tid][0], Ag + k0);
            cp_async16(&As[st][tid][4], Ag + k0 + 4);
            cp_async16(&Bs[st][br0][bc0], Bg + (size_t)(k0 + br0) * 1024 + bc0);
            cp_async16(&Bs[st][br1][bc1], Bg + (size_t)(k0 + br1) * 1024 + bc1);
            asm volatile("cp.async.commit_group;\n");
        }
    }

    // epilogue: scale by dcoef, store fp16 Z
    size_t zb = (size_t)b * MTOT * NTOT;
    #pragma unroll
    for (int i = 0; i < 4; i++) {
        int r0 = bM * 128 + wM + i * 16 + gid;
        int r1 = r0 + 8;
        float s0 = g_dcoef[b*512 + (r0 & 511)];
        float s1 = g_dcoef[b*512 + (r1 & 511)];
        #pragma unroll
        for (int j = 0; j < 8; j++) {
            int n = bN * 128 + wN + j * 8 + tig * 2;
            __half2 h0 = __floats2half2_rn(c[i][j][0] * s0, c[i][j][1] * s0);
            __half2 h1 = __floats2half2_rn(c[i][j][2] * s1, c[i][j][3] * s1);
            *(__half2*)(g_Zh + zb + (size_t)r0 * 1024 + n) = h0;
            *(__half2*)(g_Zh + zb + (size_t)r1 * 1024 + n) = h1;
        }
    }
}

// ---------------------------------------------------------------------------
// K3: upsample-scatter + FIR + noise + bias + lrelu + clamp, per (b,co) block.
// ---------------------------------------------------------------------------
__global__ void fir_kernel(const float* __restrict__ noise,
                           const float* __restrict__ nstr,
                           const float* __restrict__ bias,
                           float* __restrict__ out) {
    int co = blockIdx.x, b = blockIdx.y, tid = threadIdx.x;
    __shared__ float Zs[9][34][34];
    float* zf = &Zs[0][0][0];
    for (int i = tid; i < 9 * 34 * 34; i += 256) zf[i] = 0.f;
    __syncthreads();

    #pragma unroll
    for (int t = 0; t < 9; t++) {
        const uint2 raw = ((const uint2*)(g_Zh + (((size_t)(b*9 + t) * 512 + co) << 10)))[tid];
        __half2 p0 = *(const __half2*)&raw.x;
        __half2 p1 = *(const __half2*)&raw.y;
        float2 f0 = __half22float2(p0);
        float2 f1 = __half22float2(p1);
        int iy = tid >> 3;
        int ix = (tid & 7) * 4;
        Zs[t][1 + iy][1 + ix] = f0.x;
        Zs[t][1 + iy][2 + ix] = f0.y;
        Zs[t][1 + iy][3 + ix] = f1.x;
        Zs[t][1 + iy][4 + ix] = f1.y;
    }
    __syncthreads();

    float ns = nstr[0], bi = bias[co];
    const float cf[2][3][3] = {
        { {0.00f, 0.75f, 0.25f}, {0.25f, 0.75f, 0.00f}, {0.75f, 0.25f, 0.00f} },
        { {0.00f, 0.25f, 0.75f}, {0.00f, 0.75f, 0.25f}, {0.25f, 0.75f, 0.00f} }
    };
    size_t obase = ((size_t)(b * 512 + co)) << 12;

    for (int q = tid; q < 1024; q += 256) {
        int m = q >> 5, n = q & 31;
        float a00 = 0.f, a01 = 0.f, a10 = 0.f, a11 = 0.f;
        #pragma unroll
        for (int kh = 0; kh < 3; kh++) {
            #pragma unroll
            for (int kw = 0; kw < 3; kw++) {
                float z[3][3];
                #pragma unroll
                for (int dy = 0; dy < 3; dy++)
                    #pragma unroll
                    for (int dx = 0; dx < 3; dx++)
                        z[dy][dx] = Zs[kh * 3 + kw][m + dy][n + dx];
                #pragma unroll
                for (int dx = 0; dx < 3; dx++) {
                    float r0 = cf[0][kh][0]*z[0][dx] + cf[0][kh][1]*z[1][dx] + cf[0][kh][2]*z[2][dx];
                    float r1 = cf[1][kh][0]*z[0][dx] + cf[1][kh][1]*z[1][dx] + cf[1][kh][2]*z[2][dx];
                    a00 += cf[0][kw][dx] * r0;
                    a01 += cf[1][kw][dx] * r0;
                    a10 += cf[0][kw][dx] * r1;
                    a11 += cf[1][kw][dx] * r1;
                }
            }
        }
        int Y = 2 * m, X = 2 * n;
        float v00 = a00 + noise[(b << 12) + (Y << 6) + X    ] * ns + bi;
        float v01 = a01 + noise[(b << 12) + (Y << 6) + X + 1] * ns + bi;
        float v10 = a10 + noise[(b << 12) + ((Y+1) << 6) + X    ] * ns + bi;
        float v11 = a11 + noise[(b << 12) + ((Y+1) << 6) + X + 1] * ns + bi;
        v00 = (v00 > 0.f ? v00 : 0.2f * v00) * 1.4142135623730951f;
        v01 = (v01 > 0.f ? v01 : 0.2f * v01) * 1.4142135623730951f;
        v10 = (v10 > 0.f ? v10 : 0.2f * v10) * 1.4142135623730951f;
        v11 = (v11 > 0.f ? v11 : 0.2f * v11) * 1.4142135623730951f;
        v00 = fminf(fmaxf(v00, -256.f), 256.f);
        v01 = fminf(fmaxf(v01, -256.f), 256.f);
        v10 = fminf(fmaxf(v10, -256.f), 256.f);
        v11 = fminf(fmaxf(v11, -256.f), 256.f);
        *(float2*)(out + obase + (size_t)Y * 64 + X)       = make_float2(v00, v01);
        *(float2*)(out + obase + (size_t)(Y + 1) * 64 + X) = make_float2(v10, v11);
    }
}

// ---------------------------------------------------------------------------
extern "C" void kernel_launch(void* const* d_in, const int* in_sizes, int n_in,
                              void* d_out, int out_size) {
    const float* x     = (const float*)d_in[0];
    const float* wl    = (const float*)d_in[1];
    const float* aw    = (const float*)d_in[2];
    const float* ab    = (const float*)d_in[3];
    const float* cw    = (const float*)d_in[4];
    const float* noise = (const float*)d_in[5];
    const float* nstr  = (const float*)d_in[6];
    const float* bias  = (const float*)d_in[7];
    float* out = (float*)d_out;

    style_kernel<<<dim3(4, 16), 128>>>(wl, aw, ab);
    wprep_kernel<<<512, 512>>>(cw);
    xs_kernel<<<4096, 256>>>(x);
    gemm_kernel<<<dim3(8, 36, 16), 128>>>();
    fir_kernel<<<dim3(512, 16), 256>>>(noise, nstr, bias, out);
}

// round 9
// speedup vs baseline: 1.7008x; 1.0757x over previous
#include <cuda_runtime.h>
#include <cuda_fp16.h>
#include <cuda_bf16.h>

// ---------------------------------------------------------------------------
// SynthesisConv (StyleGAN2): modulated transposed conv up=2 + FIR + noise
//   B=16, Cin=Cout=512, H=W=32, K=3, out [16,512,64,64] fp32
//
//   style[b,ci]  = w_latent[b]·affine_weight[ci]/sqrt(512) + affine_bias[ci]
//   dcoef[b,co]  = rsqrt( sum_ci style^2 * (sum_tap w^2) + 1e-8 )
//   Z[b,tap,co,s]= dcoef * sum_ci W[co,ci,tap] * (x*style)[b,ci,s]  (FP16 GEMM)
//   out = clamp(lrelu(FIR_gather(Z) + noise*ns + bias)*sqrt2, +-256)
// ---------------------------------------------------------------------------

#define BATCH 16
#define CIN   512
#define COUT  512
#define HSP   1024
#define MTOT  4608          // 9*512
#define NTOT  1024

__device__ float  g_style[BATCH*CIN];
__device__ float  g_dcoef[BATCH*COUT];
__device__ __half g_Ah[MTOT*CIN];                  // weights [tap*512+co][ci]
__device__ __half g_xsh[BATCH*CIN*HSP];            // x*style, (ci,ci+1) pair-interleaved
__device__ __half g_Zh[(size_t)BATCH*MTOT*NTOT];   // tap GEMM outputs (post-dcoef)

__device__ __forceinline__ void cp_async16(void* smem, const void* gmem) {
    unsigned int s = (unsigned int)__cvta_generic_to_shared(smem);
    asm volatile("cp.async.cg.shared.global [%0], [%1], 16;\n" :: "r"(s), "l"(gmem));
}

__device__ __forceinline__ void mma_f16(float* c, const unsigned int* a, const unsigned int* b) {
    asm volatile(
        "mma.sync.aligned.m16n8k16.row.col.f32.f16.f16.f32 "
        "{%0,%1,%2,%3}, {%4,%5,%6,%7}, {%8,%9}, {%0,%1,%2,%3};\n"
        : "+f"(c[0]), "+f"(c[1]), "+f"(c[2]), "+f"(c[3])
        : "r"(a[0]), "r"(a[1]), "r"(a[2]), "r"(a[3]), "r"(b[0]), "r"(b[1]));
}

// ---------------------------------------------------------------------------
// K1a: style[b,ci]
// ---------------------------------------------------------------------------
__global__ void style_kernel(const float* __restrict__ wl,
                             const float* __restrict__ aw,
                             const float* __restrict__ ab) {
    int b   = blockIdx.y;
    int tid = threadIdx.x;
    int ci  = blockIdx.x * 128 + tid;
    __shared__ float s[512];
    for (int i = tid; i < 512; i += 128) s[i] = wl[b*512 + i];
    __syncthreads();
    const float4* row = (const float4*)(aw + (size_t)ci * 512);
    const float4* sw  = (const float4*)s;
    float acc = 0.f;
    #pragma unroll 4
    for (int j = 0; j < 128; j++) {
        float4 v = row[j];
        float4 w = sw[j];
        acc += v.x*w.x + v.y*w.y + v.z*w.z + v.w*w.w;
    }
    g_style[b*512 + ci] = acc * 0.04419417382415922f + ab[ci];  // 1/sqrt(512)
}

// ---------------------------------------------------------------------------
// K1b: repack weights to fp16 A[tap*512+co][ci], compute dcoef[b,co]
// single-barrier reduction: red[b][warp] partials, per-warp final reduce
// ---------------------------------------------------------------------------
__global__ void wprep_kernel(const float* __restrict__ cw) {
    int co = blockIdx.x;
    int ci = threadIdx.x;            // 512 threads = 16 warps
    const float* wrow = cw + ((size_t)co * 512 + ci) * 9;
    float w[9];
    float wsq = 0.f;
    #pragma unroll
    for (int t = 0; t < 9; t++) { w[t] = wrow[t]; wsq += w[t]*w[t]; }
    #pragma unroll
    for (int t = 0; t < 9; t++)
        g_Ah[((size_t)(t*512 + co)) * 512 + ci] = __float2half_rn(w[t]);

    __shared__ float red[16][16];    // [b][warp]
    int lane = ci & 31, warp = ci >> 5;
    #pragma unroll
    for (int b = 0; b < 16; b++) {
        float s = g_style[b*512 + ci];
        float v = s * s * wsq;
        #pragma unroll
        for (int o = 16; o; o >>= 1) v += __shfl_xor_sync(0xffffffffu, v, o);
        if (lane == 0) red[b][warp] = v;
    }
    __syncthreads();
    // warp w reduces batch b=w
    float t = (lane < 16) ? red[warp][lane] : 0.f;
    #pragma unroll
    for (int o = 8; o; o >>= 1) t += __shfl_xor_sync(0xffffffffu, t, o);
    if (lane == 0) g_dcoef[warp*512 + co] = rsqrtf(t + 1e-8f);
}

// ---------------------------------------------------------------------------
// K1c: xs = fp16(x * style), pair-interleaved: word (b,kp,s) = (ci=2kp, ci=2kp+1)
// ---------------------------------------------------------------------------
__global__ void xs_kernel(const float* __restrict__ x) {
    int idx = blockIdx.x * 256 + threadIdx.x;   // 1,048,576; each does 4 s
    int s4  = (idx & 255) * 4;
    int bkp = idx >> 8;
    int b   = bkp >> 8;
    int kp  = bkp & 255;
    const float4 v0 = *(const float4*)(x + ((size_t)(b*512 + 2*kp    ) * 1024 + s4));
    const float4 v1 = *(const float4*)(x + ((size_t)(b*512 + 2*kp + 1) * 1024 + s4));
    float s0 = g_style[b*512 + 2*kp];
    float s1 = g_style[b*512 + 2*kp + 1];
    __half2 h0 = __floats2half2_rn(v0.x*s0, v1.x*s1);
    __half2 h1 = __floats2half2_rn(v0.y*s0, v1.y*s1);
    __half2 h2 = __floats2half2_rn(v0.z*s0, v1.z*s1);
    __half2 h3 = __floats2half2_rn(v0.w*s0, v1.w*s1);
    uint4 o;
    o.x = *(unsigned int*)&h0;
    o.y = *(unsigned int*)&h1;
    o.z = *(unsigned int*)&h2;
    o.w = *(unsigned int*)&h3;
    ((uint4*)g_xsh)[idx] = o;
}

// ---------------------------------------------------------------------------
// K2: batched FP16 GEMM  Z[b] (4608x1024) = A (4608x512) * xs[b] (512x1024)
// BM=128 BN=256 BK=32, 256 threads (8 warps 2x4), warp tile 64x64,
// 4-stage cp.async pipeline (dynamic smem 108.5KB), 1 barrier per k-tile.
// epilogue: row scale by dcoef[b, m%512], store fp16.
// ---------------------------------------------------------------------------
#define APITCH 20
#define BPITCH 264
#define ASTG   (128*APITCH)   // 2560 u32 per stage
#define BSTG   (16*BPITCH)    // 4224 u32 per stage
#define GEMM_SMEM ((4*ASTG + 4*BSTG) * 4)   // 108544 bytes

__global__ __launch_bounds__(256, 1) void gemm_kernel() {
    extern __shared__ unsigned int sm[];
    unsigned int* As = sm;              // [4][128][APITCH]
    unsigned int* Bs = sm + 4*ASTG;     // [4][16][BPITCH]

    int tid = threadIdx.x;
    int bN = blockIdx.x, bM = blockIdx.y, b = blockIdx.z;
    int wid = tid >> 5, lane = tid & 31;
    int wM = (wid & 1) * 64, wN = (wid >> 1) * 64;
    int gid = lane >> 2, tig = lane & 3;

    // A cp: row = tid>>1 (0..127), 2x16B at u32 cols (tid&1)*8, +4
    int arow = tid >> 1, acb = (tid & 1) * 8;
    const unsigned int* AgRow = ((const unsigned int*)g_Ah) + ((size_t)(bM*128 + arow)) * 256;
    const unsigned int* Bg = ((const unsigned int*)g_xsh) + (size_t)b * 262144 + bN * 256;

    float c[4][8][4];
    #pragma unroll
    for (int i = 0; i < 4; i++)
        #pragma unroll
        for (int j = 0; j < 8; j++)
            #pragma unroll
            for (int k = 0; k < 4; k++) c[i][j][k] = 0.f;

    auto loadStage = [&](int st, int kt) {
        unsigned int* Asb = As + st * ASTG;
        cp_async16(Asb + arow*APITCH + acb,     AgRow + kt*16 + acb);
        cp_async16(Asb + arow*APITCH + acb + 4, AgRow + kt*16 + acb + 4);
        unsigned int* Bsb = Bs + st * BSTG;
        #pragma unroll
        for (int p = 0; p < 4; p++) {
            int idx = tid + p * 256;
            int brow = idx >> 6, bcol = (idx & 63) * 4;
            cp_async16(Bsb + brow*BPITCH + bcol, Bg + (size_t)(kt*16 + brow) * 1024 + bcol);
        }
        asm volatile("cp.async.commit_group;\n");
    };

    loadStage(0, 0);
    loadStage(1, 1);
    loadStage(2, 2);

    for (int kt = 0; kt < 16; kt++) {
        if (kt < 14) asm volatile("cp.async.wait_group 2;\n");
        else         asm volatile("cp.async.wait_group 0;\n");
        __syncthreads();

        int cur = kt & 3;
        const unsigned int* Asb = As + cur * ASTG;
        const unsigned int* Bsb = Bs + cur * BSTG;

        #pragma unroll
        for (int ks = 0; ks < 2; ks++) {
            int k8 = ks * 8;
            unsigned int a[4][4], bb[8][2];
            #pragma unroll
            for (int i = 0; i < 4; i++) {
                int mb = wM + i * 16;
                a[i][0] = Asb[(mb + gid    ) * APITCH + k8 + tig];
                a[i][1] = Asb[(mb + gid + 8) * APITCH + k8 + tig];
                a[i][2] = Asb[(mb + gid    ) * APITCH + k8 + tig + 4];
                a[i][3] = Asb[(mb + gid + 8) * APITCH + k8 + tig + 4];
            }
            #pragma unroll
            for (int j = 0; j < 8; j++) {
                int nb = wN + j * 8 + gid;
                bb[j][0] = Bsb[(k8 + tig    ) * BPITCH + nb];
                bb[j][1] = Bsb[(k8 + tig + 4) * BPITCH + nb];
            }
            #pragma unroll
            for (int i = 0; i < 4; i++)
                #pragma unroll
                for (int j = 0; j < 8; j++)
                    mma_f16(c[i][j], a[i], bb[j]);
        }

        if (kt < 13) loadStage((kt + 3) & 3, kt + 3);
    }

    // epilogue: scale by dcoef, store fp16 Z
    size_t zb = (size_t)b * MTOT * NTOT;
    #pragma unroll
    for (int i = 0; i < 4; i++) {
        int r0 = bM * 128 + wM + i * 16 + gid;
        int r1 = r0 + 8;
        float s0 = g_dcoef[b*512 + (r0 & 511)];
        float s1 = g_dcoef[b*512 + (r1 & 511)];
        #pragma unroll
        for (int j = 0; j < 8; j++) {
            int n = bN * 256 + wN + j * 8 + tig * 2;
            __half2 h0 = __floats2half2_rn(c[i][j][0] * s0, c[i][j][1] * s0);
            __half2 h1 = __floats2half2_rn(c[i][j][2] * s1, c[i][j][3] * s1);
            *(__half2*)(g_Zh + zb + (size_t)r0 * 1024 + n) = h0;
            *(__half2*)(g_Zh + zb + (size_t)r1 * 1024 + n) = h1;
        }
    }
}

// ---------------------------------------------------------------------------
// K3: separable FIR + noise + bias + lrelu + clamp, per (b,co) block.
// Pass1 (vertical): G[kw*2+ry][m][j] = sum_{kh,dy} cf[ry][kh][dy]*Z[kh*3+kw][m+dy][j]
// Pass2 (horizontal): out(2m+ry,2n+rx) = sum_{kw,dx} cf[rx][kw][dx]*G[kw*2+ry][m][n+dx]
// ---------------------------------------------------------------------------
__global__ __launch_bounds__(256) void fir_kernel(const float* __restrict__ noise,
                                                  const float* __restrict__ nstr,
                                                  const float* __restrict__ bias,
                                                  float* __restrict__ out) {
    int co = blockIdx.x, b = blockIdx.y, tid = threadIdx.x;
    __shared__ __half Zs[9][34][36];   // 22.0 KB (1-pad borders, pitch 36)
    __shared__ __half G[6][32][36];    // 13.8 KB

    // zero Zs (borders matter)
    unsigned int* zf = (unsigned int*)&Zs[0][0][0];
    for (int i = tid; i < 9 * 34 * 36 / 2; i += 256) zf[i] = 0u;
    __syncthreads();

    #pragma unroll
    for (int t = 0; t < 9; t++) {
        const uint2 raw = ((const uint2*)(g_Zh + (((size_t)(b*9 + t) * 512 + co) << 10)))[tid];
        __half2 p0 = *(const __half2*)&raw.x;
        __half2 p1 = *(const __half2*)&raw.y;
        int iy = tid >> 3;
        int ix = (tid & 7) * 4;
        Zs[t][1 + iy][1 + ix] = __low2half(p0);
        Zs[t][1 + iy][2 + ix] = __high2half(p0);
        Zs[t][1 + iy][3 + ix] = __low2half(p1);
        Zs[t][1 + iy][4 + ix] = __high2half(p1);
    }
    __syncthreads();

    // cf[parity][k][d]
    const float cf0[3][3] = { {0.00f, 0.75f, 0.25f}, {0.25f, 0.75f, 0.00f}, {0.75f, 0.25f, 0.00f} };
    const float cf1[3][3] = { {0.00f, 0.25f, 0.75f}, {0.00f, 0.75f, 0.25f}, {0.25f, 0.75f, 0.00f} };

    // pass 1: 3 kw * 32 m * 34 j = 3264 entries
    for (int e = tid; e < 3264; e += 256) {
        int kw = e / 1088;
        int r  = e - kw * 1088;
        int m  = r / 34;
        int j  = r - m * 34;
        float a0 = 0.f, a1 = 0.f;
        #pragma unroll
        for (int kh = 0; kh < 3; kh++) {
            #pragma unroll
            for (int dy = 0; dy < 3; dy++) {
                float z = __half2float(Zs[kh*3 + kw][m + dy][j]);
                a0 += cf0[kh][dy] * z;
                a1 += cf1[kh][dy] * z;
            }
        }
        G[kw*2    ][m][j] = __float2half(a0);
        G[kw*2 + 1][m][j] = __float2half(a1);
    }
    __syncthreads();

    float ns = nstr[0], bi = bias[co];
    size_t obase = ((size_t)(b * 512 + co)) << 12;

    // pass 2: 1024 (m,n) pairs, 4 iters/thread
    for (int q = tid; q < 1024; q += 256) {
        int m = q >> 5, n = q & 31;
        float o00 = 0.f, o01 = 0.f, o10 = 0.f, o11 = 0.f;
        #pragma unroll
        for (int kw = 0; kw < 3; kw++) {
            #pragma unroll
            for (int dx = 0; dx < 3; dx++) {
                float g0 = __half2float(G[kw*2    ][m][n + dx]);
                float g1 = __half2float(G[kw*2 + 1][m][n + dx]);
                o00 += cf0[kw][dx] * g0;
                o01 += cf1[kw][dx] * g0;
                o10 += cf0[kw][dx] * g1;
                o11 += cf1[kw][dx] * g1;
            }
        }
        int Y = 2 * m, X = 2 * n;
        float v00 = o00 + noise[(b << 12) + (Y << 6) + X    ] * ns + bi;
        float v01 = o01 + noise[(b << 12) + (Y << 6) + X + 1] * ns + bi;
        float v10 = o10 + noise[(b << 12) + ((Y+1) << 6) + X    ] * ns + bi;
        float v11 = o11 + noise[(b << 12) + ((Y+1) << 6) + X + 1] * ns + bi;
        v00 = (v00 > 0.f ? v00 : 0.2f * v00) * 1.4142135623730951f;
        v01 = (v01 > 0.f ? v01 : 0.2f * v01) * 1.4142135623730951f;
        v10 = (v10 > 0.f ? v10 : 0.2f * v10) * 1.4142135623730951f;
        v11 = (v11 > 0.f ? v11 : 0.2f * v11) * 1.4142135623730951f;
        v00 = fminf(fmaxf(v00, -256.f), 256.f);
        v01 = fminf(fmaxf(v01, -256.f), 256.f);
        v10 = fminf(fmaxf(v10, -256.f), 256.f);
        v11 = fminf(fmaxf(v11, -256.f), 256.f);
        *(float2*)(out + obase + (size_t)Y * 64 + X)       = make_float2(v00, v01);
        *(float2*)(out + obase + (size_t)(Y + 1) * 64 + X) = make_float2(v10, v11);
    }
}

// ---------------------------------------------------------------------------
extern "C" void kernel_launch(void* const* d_in, const int* in_sizes, int n_in,
                              void* d_out, int out_size) {
    const float* x     = (const float*)d_in[0];
    const float* wl    = (const float*)d_in[1];
    const float* aw    = (const float*)d_in[2];
    const float* ab    = (const float*)d_in[3];
    const float* cw    = (const float*)d_in[4];
    const float* noise = (const float*)d_in[5];
    const float* nstr  = (const float*)d_in[6];
    const float* bias  = (const float*)d_in[7];
    float* out = (float*)d_out;

    cudaFuncSetAttribute(gemm_kernel, cudaFuncAttributeMaxDynamicSharedMemorySize, GEMM_SMEM);

    style_kernel<<<dim3(4, 16), 128>>>(wl, aw, ab);
    wprep_kernel<<<512, 512>>>(cw);
    xs_kernel<<<4096, 256>>>(x);
    gemm_kernel<<<dim3(4, 36, 16), 256, GEMM_SMEM>>>();
    fir_kernel<<<dim3(512, 16), 256>>>(noise, nstr, bias, out);
}